// round 16
// baseline (speedup 1.0000x reference)
#include <cuda_runtime.h>
#include <cuda_fp16.h>
#include <math.h>

#define NN 8192
#define DD 256
#define HH 64

// Pre-scaled features: he[j, d] = e_j * h[j, d], fp16 (4 MB, L2-resident).
__device__ __half g_he[NN * DD];

// ---------------------------------------------------------------------------
// Kernel 1: e = sigmoid(relu(h @ W1 + b1) @ W2 + b2); emit he = e*h (fp16).
// 4-WAY K-SPLIT 4x4 tile: 16 rows/block, 512 blocks, 256 threads =
//   kq (4 k-quarters) x rg (4 rowgroups x4 rows) x jg (16 jgroups x4 j).
// Per thread: 16 k4 x (4 broadcast LDS.128 + 4 W1 float4 LDG + 64 FFMA).
// Total FFMA / warp-LDG identical to the validated R15 tile; 2x warps/SM
// (27.7). Quarters 1-3 publish partials to smem; quarter 0 combines before
// relu, then the W2 dot.
// ---------------------------------------------------------------------------
#define MLP_ROWS 16
__global__ void __launch_bounds__(256) mlp_kernel(
    const float* __restrict__ h, const float* __restrict__ W1,
    const float* __restrict__ b1, const float* __restrict__ W2,
    const float* __restrict__ b2, float* __restrict__ out_e) {

  __shared__ __align__(16) float sh_h[MLP_ROWS * DD];       // 16 KB
  __shared__ __align__(16) float4 sAcc[3][MLP_ROWS][16];    // 12 KB partials
  __shared__ float sPart[MLP_ROWS][17];
  __shared__ float sE[MLP_ROWS];

  const int tid = threadIdx.x;
  const int kq = tid >> 6;                  // 0..3 -> k quarter
  const int rg = (tid >> 4) & 3;            // 0..3 -> rows rg*4 .. +3
  const int jg = tid & 15;                  // 0..15 -> j jg*4 .. +3
  const int j0 = jg * 4;
  const int rowbase = blockIdx.x * MLP_ROWS;

  // Stage 16 h rows (1024 float4 / 256 thr = 4 each), coalesced.
  {
    const float4* src = (const float4*)(h + (size_t)rowbase * DD);
    float4* dst = (float4*)sh_h;
    #pragma unroll
    for (int i = tid; i < MLP_ROWS * DD / 4; i += 256) dst[i] = __ldg(&src[i]);
  }
  __syncthreads();

  float acc[4][4];
  if (kq == 0) {
    const float4 b = __ldg((const float4*)(b1 + j0));
    #pragma unroll
    for (int a = 0; a < 4; a++) {
      acc[a][0] = b.x; acc[a][1] = b.y; acc[a][2] = b.z; acc[a][3] = b.w;
    }
  } else {
    #pragma unroll
    for (int a = 0; a < 4; a++)
      #pragma unroll
      for (int c = 0; c < 4; c++) acc[a][c] = 0.0f;
  }

  const float4* sh4 = (const float4*)sh_h;
  const float4* W14 = (const float4*)W1;    // row k = 16 float4 over j

  #pragma unroll 4
  for (int k4 = 0; k4 < 16; k4++) {
    const int kg = kq * 16 + k4;
    float4 hv[4];
    #pragma unroll
    for (int a = 0; a < 4; a++)
      hv[a] = sh4[(rg * 4 + a) * (DD / 4) + kg];          // broadcast

    const float4 wA = __ldg(&W14[(kg * 4 + 0) * 16 + jg]);
    const float4 wB = __ldg(&W14[(kg * 4 + 1) * 16 + jg]);
    const float4 wC = __ldg(&W14[(kg * 4 + 2) * 16 + jg]);
    const float4 wD = __ldg(&W14[(kg * 4 + 3) * 16 + jg]);

    #pragma unroll
    for (int a = 0; a < 4; a++) {
      acc[a][0] = fmaf(hv[a].x, wA.x, fmaf(hv[a].y, wB.x, fmaf(hv[a].z, wC.x, fmaf(hv[a].w, wD.x, acc[a][0]))));
      acc[a][1] = fmaf(hv[a].x, wA.y, fmaf(hv[a].y, wB.y, fmaf(hv[a].z, wC.y, fmaf(hv[a].w, wD.y, acc[a][1]))));
      acc[a][2] = fmaf(hv[a].x, wA.z, fmaf(hv[a].y, wB.z, fmaf(hv[a].z, wC.z, fmaf(hv[a].w, wD.z, acc[a][2]))));
      acc[a][3] = fmaf(hv[a].x, wA.w, fmaf(hv[a].y, wB.w, fmaf(hv[a].z, wC.w, fmaf(hv[a].w, wD.w, acc[a][3]))));
    }
  }

  // Quarters 1..3 publish partials; quarter 0 combines, relu, W2 dot.
  if (kq != 0) {
    #pragma unroll
    for (int a = 0; a < 4; a++)
      sAcc[kq - 1][rg * 4 + a][jg] =
          make_float4(acc[a][0], acc[a][1], acc[a][2], acc[a][3]);
  }
  __syncthreads();

  if (kq == 0) {
    const float4 w2 = __ldg((const float4*)(W2 + j0));
    #pragma unroll
    for (int a = 0; a < 4; a++) {
      const float4 o1 = sAcc[0][rg * 4 + a][jg];
      const float4 o2 = sAcc[1][rg * 4 + a][jg];
      const float4 o3 = sAcc[2][rg * 4 + a][jg];
      const float t0 = acc[a][0] + o1.x + o2.x + o3.x;
      const float t1 = acc[a][1] + o1.y + o2.y + o3.y;
      const float t2 = acc[a][2] + o1.z + o2.z + o3.z;
      const float t3 = acc[a][3] + o1.w + o2.w + o3.w;
      sPart[rg * 4 + a][jg] =
          fmaxf(t0, 0.0f) * w2.x + fmaxf(t1, 0.0f) * w2.y +
          fmaxf(t2, 0.0f) * w2.z + fmaxf(t3, 0.0f) * w2.w;
    }
  }
  __syncthreads();

  if (tid < MLP_ROWS) {
    float s = __ldg(&b2[0]);
    #pragma unroll
    for (int g = 0; g < 16; g++) s += sPart[tid][g];
    const float ev = 1.0f / (1.0f + expf(-s));
    sE[tid] = ev;
    out_e[rowbase + tid] = ev;
  }
  __syncthreads();

  // Emit he16 = e_row * h from smem (4 float4 per thread).
  __half2* he2 = (__half2*)g_he;
  #pragma unroll
  for (int i = tid; i < MLP_ROWS * (DD / 4); i += 256) {
    const int r = i >> 6;
    const float4 hv = ((const float4*)sh_h)[i];
    const float e = sE[r];
    const size_t base = ((size_t)rowbase * DD + i * 4) >> 1;
    he2[base]     = __floats2half2_rn(hv.x * e, hv.y * e);
    he2[base + 1] = __floats2half2_rn(hv.z * e, hv.w * e);
  }
}

// ---------------------------------------------------------------------------
// Kernel 2 (EXACT R10 agg — measured 50.75-52.7 over 5 runs, LTS ceiling):
// h_out[i,:] = sum_{j: A[i,j] > 0} he[j,:]
// One block (8 warps) per row; each warp independent on its 1/8 slice:
//   scan: 8 front-batched __ldcs uint4 -> 32-bit register pending mask
//   gather: per round, 1 ballot picks up to 4 source lanes; shfl their j's;
//           4 independent warp-LDG.128 of fp16 he rows; owners clear a bit.
// Single __syncthreads per row (cross-warp reduce).
// ---------------------------------------------------------------------------
__global__ void __launch_bounds__(256) agg_kernel(const float* __restrict__ A,
                                                  float* __restrict__ out) {
  __shared__ __align__(16) float s_red[8][DD];   // 8 KB

  const int row = blockIdx.x;
  const int tid = threadIdx.x;
  const int wid = tid >> 5;
  const int lane = tid & 31;

  const uint4* Aslice = (const uint4*)(A + (size_t)row * NN) + wid * 256;

  uint4 av[8];
  #pragma unroll
  for (int r = 0; r < 8; r++)
    av[r] = __ldcs(Aslice + r * 32 + lane);

  unsigned pending = 0u;
  #pragma unroll
  for (int r = 0; r < 8; r++) {
    unsigned f = 0u;
    if (av[r].x) f |= 1u;
    if (av[r].y) f |= 2u;
    if (av[r].z) f |= 4u;
    if (av[r].w) f |= 8u;
    pending |= f << (r * 4);
  }

  const uint4* he4 = (const uint4*)g_he;
  float acc[8] = {0.f, 0.f, 0.f, 0.f, 0.f, 0.f, 0.f, 0.f};

  while (true) {
    unsigned m = __ballot_sync(0xFFFFFFFFu, pending != 0u);
    if (!m) break;

    const int b = __ffs(pending) - 1;
    const int jmine = wid * 1024 + ((b & ~3) << 5) + (lane << 2) + (b & 3);

    const int n = __popc(m) < 4 ? __popc(m) : 4;
    int s0 = __ffs(m) - 1;            m &= m - 1;
    int s1 = m ? __ffs(m) - 1 : s0;   m &= m - 1;
    int s2 = m ? __ffs(m) - 1 : s0;   m &= m - 1;
    int s3 = m ? __ffs(m) - 1 : s0;

    const int j0 = __shfl_sync(0xFFFFFFFFu, jmine, s0);
    const int j1 = __shfl_sync(0xFFFFFFFFu, jmine, s1);
    const int j2 = __shfl_sync(0xFFFFFFFFu, jmine, s2);
    const int j3 = __shfl_sync(0xFFFFFFFFu, jmine, s3);

    if (lane == s0 || (n > 1 && lane == s1) || (n > 2 && lane == s2) ||
        (n > 3 && lane == s3))
      pending &= pending - 1u;

    uint4 v0, v1, v2, v3;
    v0 = __ldg(&he4[(size_t)j0 * 32 + lane]);
    if (n > 1) v1 = __ldg(&he4[(size_t)j1 * 32 + lane]);
    if (n > 2) v2 = __ldg(&he4[(size_t)j2 * 32 + lane]);
    if (n > 3) v3 = __ldg(&he4[(size_t)j3 * 32 + lane]);

    {
      const __half2* p = (const __half2*)&v0;
      #pragma unroll
      for (int q = 0; q < 4; q++) {
        const float2 f = __half22float2(p[q]);
        acc[2 * q] += f.x; acc[2 * q + 1] += f.y;
      }
    }
    if (n > 1) {
      const __half2* p = (const __half2*)&v1;
      #pragma unroll
      for (int q = 0; q < 4; q++) {
        const float2 f = __half22float2(p[q]);
        acc[2 * q] += f.x; acc[2 * q + 1] += f.y;
      }
    }
    if (n > 2) {
      const __half2* p = (const __half2*)&v2;
      #pragma unroll
      for (int q = 0; q < 4; q++) {
        const float2 f = __half22float2(p[q]);
        acc[2 * q] += f.x; acc[2 * q + 1] += f.y;
      }
    }
    if (n > 3) {
      const __half2* p = (const __half2*)&v3;
      #pragma unroll
      for (int q = 0; q < 4; q++) {
        const float2 f = __half22float2(p[q]);
        acc[2 * q] += f.x; acc[2 * q + 1] += f.y;
      }
    }
  }

  {
    float4* rr = (float4*)s_red[wid];
    rr[lane * 2]     = make_float4(acc[0], acc[1], acc[2], acc[3]);
    rr[lane * 2 + 1] = make_float4(acc[4], acc[5], acc[6], acc[7]);
  }
  __syncthreads();

  float s = 0.0f;
  #pragma unroll
  for (int w = 0; w < 8; w++) s += s_red[w][tid];
  out[(size_t)row * DD + tid] = s;
}

// ---------------------------------------------------------------------------
// Inputs (setup_inputs order):
//   0: graph_info [N*N], 1: h [N*D], 2: W1 [D*H], 3: b1 [H], 4: W2 [H], 5: b2 [1]
// Output: h_out [N*D] followed by e [N].
// ---------------------------------------------------------------------------
extern "C" void kernel_launch(void* const* d_in, const int* in_sizes, int n_in,
                              void* d_out, int out_size) {
  const float* A  = (const float*)d_in[0];
  const float* h  = (const float*)d_in[1];
  const float* W1 = (const float*)d_in[2];
  const float* b1 = (const float*)d_in[3];
  const float* W2 = (const float*)d_in[4];
  const float* b2 = (const float*)d_in[5];

  float* out_h = (float*)d_out;                     // [N*D]
  float* out_e = (float*)d_out + (size_t)NN * DD;   // [N]

  mlp_kernel<<<NN / MLP_ROWS, 256>>>(h, W1, b1, W2, b2, out_e);
  agg_kernel<<<NN, 256>>>(A, out_h);
}